// round 5
// baseline (speedup 1.0000x reference)
#include <cuda_runtime.h>
#include <math.h>

#define Bq   4
#define Nn   192
#define Hh   128
#define NBt  3
#define ROWS (Bq*Nn)       // 768
#define EMAX (ROWS*Nn)
#define TE   16            // edges per tile
#define FST  12            // feature stride (floats)
#define SHS  20            // sh row stride (floats)
#define GRID_E 1184

typedef unsigned long long ull;

// ---- scratch (device globals) ----
__device__ float g_F[ROWS*Hh];
__device__ float g_preA[ROWS*Hh];
__device__ float g_preB[ROWS*Hh];
__device__ float g_agg[ROWS*Hh];
__device__ int   g_cnt[ROWS];
__device__ int   g_nE;
__device__ int   g_eI[EMAX];
__device__ int   g_eJ[EMAX];
__device__ float g_feat[(size_t)EMAX*FST];
__device__ __align__(16) ull   g_Wcd[NBt*256*128];      // folded weights, duplicated pairs
__device__ __align__(16) float g_cvec[NBt*Hh];
// transposed weights: per t, row h (1024 floats): [W1a:0-127 | W1b:128-255 | W1c:256-383 |
//   W1d:384-511 | ew2:512-639 | nw1:640-895 | nw2:896-1023]
__device__ __align__(16) float g_WT[NBt*128*1024];
__device__ __align__(16) float g_owT[128*128];

__device__ __forceinline__ float silu_f(float x) { return x / (1.0f + __expf(-x)); }
__device__ __forceinline__ ull fma2(ull a, ull b, ull c) {
    ull d; asm("fma.rn.f32x2 %0, %1, %2, %3;" : "=l"(d) : "l"(a), "l"(b), "l"(c)); return d;
}
__device__ __forceinline__ ull pack2(float lo, float hi) {
    ull d; asm("mov.b64 %0, {%1, %2};" : "=l"(d) : "f"(lo), "f"(hi)); return d;
}
__device__ __forceinline__ void unpack2(ull v, float& lo, float& hi) {
    asm("mov.b64 {%0, %1}, %2;" : "=f"(lo), "=f"(hi) : "l"(v));
}

// vectored dot: w contiguous (LDG.128), xs smem broadcast (LDS.128). n multiple of 8.
__device__ __forceinline__ float dotN(const float* __restrict__ w, const float* xs, int n) {
    ull a0 = pack2(0.f, 0.f), a1 = pack2(0.f, 0.f);
    #pragma unroll 4
    for (int k = 0; k < n; k += 8) {
        ulonglong2 x0 = *(const ulonglong2*)&xs[k];
        ulonglong2 x1 = *(const ulonglong2*)&xs[k+4];
        ulonglong2 w0 = __ldg((const ulonglong2*)&w[k]);
        ulonglong2 w1 = __ldg((const ulonglong2*)&w[k+4]);
        a0 = fma2(x0.x, w0.x, a0);
        a1 = fma2(x0.y, w0.y, a1);
        a0 = fma2(x1.x, w1.x, a0);
        a1 = fma2(x1.y, w1.y, a1);
    }
    float l0,h0,l1,h1; unpack2(a0,l0,h0); unpack2(a1,l1,h1);
    return (l0+h0)+(l1+h1);
}

// ---- weight transpose: 3200 source rows of width 128 -> g_WT / g_owT ----
// Also resets g_nE (this kernel is first in stream order every replay).
__global__ void k_transpose(const float* __restrict__ ew1, const float* __restrict__ ew2,
                            const float* __restrict__ nw1, const float* __restrict__ nw2,
                            const float* __restrict__ ow1) {
    if (blockIdx.x == 0 && blockIdx.y == 0 && threadIdx.x == 0 && threadIdx.y == 0)
        g_nE = 0;
    __shared__ float tile[32][33];
    int kbase = blockIdx.x * 32;
    int hbase = blockIdx.y * 32;
    int tx = threadIdx.x, ty = threadIdx.y;   // 32 x 8
    #pragma unroll
    for (int rr = 0; rr < 4; rr++) {
        int kg = kbase + ty + 8*rr;
        const float* src;
        if (kg < 3072) {
            int t = kg >> 10, sec = kg & 1023;
            if (sec < 512)      src = ew1 + ((size_t)t*512 + sec)*128;
            else if (sec < 640) src = ew2 + ((size_t)t*128 + (sec-512))*128;
            else if (sec < 896) src = nw1 + ((size_t)t*256 + (sec-640))*128;
            else                src = nw2 + ((size_t)t*128 + (sec-896))*128;
        } else {
            src = ow1 + (size_t)(kg - 3072)*128;
        }
        tile[ty + 8*rr][tx] = src[hbase + tx];
    }
    __syncthreads();
    #pragma unroll
    for (int rr = 0; rr < 4; rr++) {
        int h  = hbase + ty + 8*rr;
        int kg = kbase + tx;
        float v = tile[tx][ty + 8*rr];
        if (kg < 3072) {
            int t = kg >> 10, sec = kg & 1023;
            g_WT[((size_t)(t*128 + h))*1024 + sec] = v;
        } else {
            g_owT[(size_t)h*128 + (kg - 3072)] = v;
        }
    }
}

// feats = emb[idx]; preA/preB block 0 (transposed weights); zero agg/out
__global__ void k_init(const int* __restrict__ idx, const float* __restrict__ emb,
                       float* __restrict__ out) {
    int row = blockIdx.x, h = threadIdx.x;
    __shared__ __align__(16) float xs[Hh];
    float v = emb[idx[row]*Hh + h];
    g_F[row*Hh + h] = v;
    xs[h] = v;
    g_agg[row*Hh + h] = 0.f;
    if (row == 0 && h < Bq) out[h] = 0.f;
    __syncthreads();
    const float* WT = g_WT + (size_t)h*1024;      // t = 0
    g_preA[row*Hh + h] = dotN(WT,       xs, 128);
    g_preB[row*Hh + h] = dotN(WT + 128, xs, 128);
}

// flat edge list + geometry features
__global__ void k_edges(const float* __restrict__ pos, const int* __restrict__ adj,
                        const float* __restrict__ mask,
                        const float* __restrict__ dpw, const float* __restrict__ dpb) {
    int row = blockIdx.x;
    int b = row / Nn, i = row % Nn;
    int j = threadIdx.x;
    __shared__ int s_cnt, s_base;
    if (j == 0) s_cnt = 0;
    __syncthreads();

    const float* pb = pos + (size_t)b*Nn*3;
    float xi = pb[i*3+0], yi = pb[i*3+1], zi = pb[i*3+2];
    float xj = pb[j*3+0], yj = pb[j*3+1], zj = pb[j*3+2];
    float dx = xi-xj, dy = yi-yj, dz = zi-zj;
    float dist = sqrtf(dx*dx + dy*dy + dz*dz);
    bool valid = (mask[row] > 0.f) && (mask[b*Nn + j] > 0.f) && (dist <= 5.0f)
                 && (adj[(size_t)b*Nn*Nn + (size_t)i*Nn + j] > 0) && (i != j);
    int el = -1;
    float ft[10];
    if (valid) {
        el = atomicAdd(&s_cnt, 1);
        float inv = 1.0f / (dist + 1e-8f);
        float ux = dx*inv, uy = dy*inv, uz = dz*inv;
        const float w = (5.0f/6.0f) + 1e-8f;
        #pragma unroll
        for (int r = 0; r < 6; r++) {
            float t = (dist - (float)r) / w;
            ft[r] = expf(-0.5f * t * t);
        }
        #pragma unroll
        for (int s = 0; s < 4; s++) {
            float vv = ux*dpw[0*4+s] + uy*dpw[1*4+s] + uz*dpw[2*4+s] + dpb[s];
            ft[6+s] = tanhf(vv);
        }
    }
    __syncthreads();
    if (j == 0) {
        g_cnt[row] = s_cnt;
        s_base = atomicAdd(&g_nE, s_cnt);
    }
    __syncthreads();
    if (valid) {
        int e = s_base + el;
        g_eI[e] = row;
        g_eJ[e] = b*Nn + j;
        float4* fo = (float4*)&g_feat[(size_t)e*FST];
        fo[0] = make_float4(ft[0], ft[1], ft[2], ft[3]);
        fo[1] = make_float4(ft[4], ft[5], ft[6], ft[7]);
        fo[2] = make_float4(ft[8], ft[9], 0.f, 0.f);
    }
}

// weight folding -> duplicated-pair layout; uses transposed W1c/W1d rows
__global__ void k_fold(const float* __restrict__ rw2, const float* __restrict__ rb2,
                       const float* __restrict__ dw2, const float* __restrict__ db2,
                       const float* __restrict__ eb1) {
    int h  = threadIdx.x;
    int t  = blockIdx.x / 257;
    int kk = blockIdx.x % 257;
    const float* WTh = g_WT + (size_t)(t*128 + h)*1024;
    if (kk < 256) {
        __shared__ __align__(16) float xs[Hh];
        const float* srow = (kk < 128) ? (rw2 + ((size_t)t*128 + kk)*128)
                                       : (dw2 + ((size_t)t*128 + (kk-128))*128);
        xs[h] = srow[h];
        __syncthreads();
        float s = dotN(WTh + ((kk < 128) ? 256 : 384), xs, 128);
        g_Wcd[(size_t)(t*256 + kk)*128 + h] = pack2(s, s);
    } else {
        __shared__ __align__(16) float rb[Hh];
        __shared__ __align__(16) float db[Hh];
        rb[h] = rb2[t*Hh + h];
        db[h] = db2[t*Hh + h];
        __syncthreads();
        float s = eb1[t*Hh + h] + dotN(WTh + 256, rb, 128) + dotN(WTh + 384, db, 128);
        g_cvec[t*Hh + h] = s;
    }
}

// edge MLP + aggregation: 16-edge tiles, WH=2, LDG.128 pre-duplicated weights
__global__ void __launch_bounds__(Hh, 8)
k_edge_mlp(const float* __restrict__ rw1, const float* __restrict__ rb1,
           const float* __restrict__ dw1, const float* __restrict__ db1, int t) {
    int tid = threadIdx.x;
    int hw    = tid & 63;
    int ehalf = tid >> 6;
    int eoff  = ehalf * 8;

    __shared__ __align__(16) float sh[256*SHS];
    __shared__ int s_eI[TE], s_eJ[TE];

    int nE = g_nE;
    int nT = (nE + TE - 1) / TE;
    const ull* Wcd = g_Wcd + (size_t)t*256*128;
    float2 cv = ((const float2*)g_cvec)[t*64 + hw];

    for (int tile = blockIdx.x; tile < nT; tile += gridDim.x) {
        int e0 = tile * TE;
        int ne = min(TE, nE - e0);
        __syncthreads();
        if (tid < TE) {
            int idx = (tid < ne) ? (e0 + tid) : e0;
            s_eI[tid] = g_eI[idx];
            s_eJ[tid] = g_eJ[idx];
        }
        {
            float rb1h = rb1[t*Hh + tid], db1h = db1[t*Hh + tid];
            float rw[6], dwv[4];
            #pragma unroll
            for (int r = 0; r < 6; r++) rw[r] = rw1[(t*6 + r)*Hh + tid];
            #pragma unroll
            for (int r = 0; r < 4; r++) dwv[r] = dw1[(t*4 + r)*Hh + tid];
            #pragma unroll
            for (int half = 0; half < 2; half++) {
                float va[8], vb[8];
                #pragma unroll
                for (int e = 0; e < 8; e++) {
                    int ge = half*8 + e;
                    if (ge < ne) {
                        const float4* fp = (const float4*)&g_feat[(size_t)(e0+ge)*FST];
                        float4 fa = fp[0], fb4 = fp[1], fc = fp[2];
                        float a = rb1h + fa.x*rw[0] + fa.y*rw[1] + fa.z*rw[2]
                                       + fa.w*rw[3] + fb4.x*rw[4] + fb4.y*rw[5];
                        float bb = db1h + fb4.z*dwv[0] + fb4.w*dwv[1]
                                        + fc.x*dwv[2] + fc.y*dwv[3];
                        va[e] = silu_f(a);
                        vb[e] = silu_f(bb);
                    } else { va[e] = 0.f; vb[e] = 0.f; }
                }
                float4* rowA = (float4*)&sh[tid*SHS + half*8];
                float4* rowB = (float4*)&sh[(128+tid)*SHS + half*8];
                rowA[0] = make_float4(va[0], va[1], va[2], va[3]);
                rowA[1] = make_float4(va[4], va[5], va[6], va[7]);
                rowB[0] = make_float4(vb[0], vb[1], vb[2], vb[3]);
                rowB[1] = make_float4(vb[4], vb[5], vb[6], vb[7]);
            }
        }
        __syncthreads();

        ull gA[4], gB[4];
        #pragma unroll
        for (int p = 0; p < 4; p++) {
            float2 a0 = ((const float2*)g_preA)[s_eI[eoff+2*p]*64 + hw];
            float2 b0 = ((const float2*)g_preB)[s_eJ[eoff+2*p]*64 + hw];
            float2 a1 = ((const float2*)g_preA)[s_eI[eoff+2*p+1]*64 + hw];
            float2 b1 = ((const float2*)g_preB)[s_eJ[eoff+2*p+1]*64 + hw];
            gA[p] = pack2(a0.x + b0.x + cv.x, a1.x + b1.x + cv.x);
            gB[p] = pack2(a0.y + b0.y + cv.y, a1.y + b1.y + cv.y);
        }

        #pragma unroll 8
        for (int k = 0; k < 256; k++) {
            ulonglong2 w2 = __ldg((const ulonglong2*)(Wcd + ((size_t)k << 7) + 2*hw));
            const ulonglong2 s01 = *(const ulonglong2*)&sh[k*SHS + eoff];
            const ulonglong2 s23 = *(const ulonglong2*)&sh[k*SHS + eoff + 4];
            gA[0] = fma2(s01.x, w2.x, gA[0]);
            gA[1] = fma2(s01.y, w2.x, gA[1]);
            gA[2] = fma2(s23.x, w2.x, gA[2]);
            gA[3] = fma2(s23.y, w2.x, gA[3]);
            gB[0] = fma2(s01.x, w2.y, gB[0]);
            gB[1] = fma2(s01.y, w2.y, gB[1]);
            gB[2] = fma2(s23.x, w2.y, gB[2]);
            gB[3] = fma2(s23.y, w2.y, gB[3]);
        }

        int neH = ne - eoff; neH = neH < 0 ? 0 : (neH > 8 ? 8 : neH);
        float mA[8], mB[8];
        #pragma unroll
        for (int p = 0; p < 4; p++) {
            float lo, hi;
            unpack2(gA[p], lo, hi); mA[2*p] = silu_f(lo); mA[2*p+1] = silu_f(hi);
            unpack2(gB[p], lo, hi); mB[2*p] = silu_f(lo); mB[2*p+1] = silu_f(hi);
        }
        int cur = -1; float sA = 0.f, sB = 0.f;
        int hh = 2*hw;
        #pragma unroll
        for (int e = 0; e < 8; e++) {
            if (e < neH) {
                int i = s_eI[eoff + e];
                if (i != cur) {
                    if (cur >= 0) {
                        atomicAdd(&g_agg[cur*Hh + hh],     sA);
                        atomicAdd(&g_agg[cur*Hh + hh + 1], sB);
                    }
                    cur = i; sA = mA[e]; sB = mB[e];
                } else { sA += mA[e]; sB += mB[e]; }
            }
        }
        if (cur >= 0) {
            atomicAdd(&g_agg[cur*Hh + hh],     sA);
            atomicAdd(&g_agg[cur*Hh + hh + 1], sB);
        }
    }
}

// node update via transposed weights (+ next-block pre, or output head)
__global__ void k_node(const float* __restrict__ eb2, const float* __restrict__ nb1,
                       const float* __restrict__ nb2,
                       const float* __restrict__ ob1, const float* __restrict__ ow2,
                       const float* __restrict__ ob2,
                       const float* __restrict__ mask, float* __restrict__ out, int t) {
    int row = blockIdx.x, h = threadIdx.x;
    __shared__ __align__(16) float xs[256];
    __shared__ __align__(16) float us[Hh];
    __shared__ float red[4];
    const float* WT = g_WT + (size_t)(t*128 + h)*1024;

    float fh = g_F[row*Hh + h];
    xs[h] = g_agg[row*Hh + h];
    __syncthreads();
    float deg = (float)g_cnt[row];
    float s = deg * eb2[t*Hh + h] + dotN(WT + 512, xs, 128);
    __syncthreads();
    xs[h] = fh; xs[128 + h] = s;
    __syncthreads();
    float u = silu_f(nb1[t*Hh + h] + dotN(WT + 640, xs, 256));
    us[h] = u;
    __syncthreads();
    float upd = nb2[t*Hh + h] + dotN(WT + 896, us, 128);
    float newf = fh + upd;
    g_F[row*Hh + h] = newf;

    __syncthreads();
    xs[h] = newf;
    __syncthreads();
    if (t + 1 < NBt) {
        const float* WT2 = g_WT + (size_t)((t+1)*128 + h)*1024;
        g_preA[row*Hh + h] = dotN(WT2,       xs, 128);
        g_preB[row*Hh + h] = dotN(WT2 + 128, xs, 128);
        g_agg[row*Hh + h] = 0.f;
    } else {
        float o = silu_f(ob1[h] + dotN(g_owT + (size_t)h*128, xs, 128)) * ow2[h];
        #pragma unroll
        for (int off = 16; off > 0; off >>= 1)
            o += __shfl_down_sync(0xffffffffu, o, off);
        if ((h & 31) == 0) red[h >> 5] = o;
        __syncthreads();
        if (h == 0) {
            float v = red[0] + red[1] + red[2] + red[3] + ob2[0];
            v *= mask[row];
            atomicAdd(&out[row / Nn], v);
        }
    }
}

extern "C" void kernel_launch(void* const* d_in, const int* in_sizes, int n_in,
                              void* d_out, int out_size) {
    const int*   node_indices = (const int*)  d_in[0];
    const float* positions    = (const float*)d_in[1];
    const int*   adjacency    = (const int*)  d_in[2];
    const float* mask         = (const float*)d_in[3];
    const float* emb          = (const float*)d_in[4];
    const float* dpw          = (const float*)d_in[5];
    const float* dpb          = (const float*)d_in[6];
    const float* rbf_w1 = (const float*)d_in[7];
    const float* rbf_b1 = (const float*)d_in[8];
    const float* rbf_w2 = (const float*)d_in[9];
    const float* rbf_b2 = (const float*)d_in[10];
    const float* dir_w1 = (const float*)d_in[11];
    const float* dir_b1 = (const float*)d_in[12];
    const float* dir_w2 = (const float*)d_in[13];
    const float* dir_b2 = (const float*)d_in[14];
    const float* edge_w1 = (const float*)d_in[15];
    const float* edge_b1 = (const float*)d_in[16];
    const float* edge_w2 = (const float*)d_in[17];
    const float* edge_b2 = (const float*)d_in[18];
    const float* node_w1 = (const float*)d_in[19];
    const float* node_b1 = (const float*)d_in[20];
    const float* node_w2 = (const float*)d_in[21];
    const float* node_b2 = (const float*)d_in[22];
    const float* ow1 = (const float*)d_in[23];
    const float* ob1 = (const float*)d_in[24];
    const float* ow2 = (const float*)d_in[25];
    const float* ob2 = (const float*)d_in[26];
    float* out = (float*)d_out;

    // Order matters: k_transpose resets g_nE and fills g_WT;
    // k_init (reads g_WT) must run BEFORE k_edges never — wait, k_init only
    // needs g_WT; k_edges accumulates g_nE which k_transpose reset. Sequence:
    k_transpose<<<dim3(100, 4), dim3(32, 8)>>>(edge_w1, edge_w2, node_w1, node_w2, ow1);
    k_init<<<ROWS, Hh>>>(node_indices, emb, out);
    k_edges<<<ROWS, Nn>>>(positions, adjacency, mask, dpw, dpb);
    k_fold<<<3*257, Hh>>>(rbf_w2, rbf_b2, dir_w2, dir_b2, edge_b1);
    for (int t = 0; t < NBt; t++) {
        k_edge_mlp<<<GRID_E, Hh>>>(rbf_w1, rbf_b1, dir_w1, dir_b1, t);
        k_node<<<ROWS, Hh>>>(edge_b2, node_b1, node_b2, ob1, ow2, ob2, mask, out, t);
    }
}

// round 7
// speedup vs baseline: 1.5568x; 1.5568x over previous
#include <cuda_runtime.h>
#include <math.h>

#define Bq   4
#define Nn   192
#define Hh   128
#define NBt  3
#define ROWS (Bq*Nn)       // 768
#define EMAX (ROWS*Nn)
#define TE   64            // edges per tile
#define FST  12            // feature stride (floats)
#define SHS  68            // sh row stride (floats): 272B, 16B-aligned, ≡4 mod 32 banks
#define GRID_E 444
#define SH_BYTES (256*SHS*4)

typedef unsigned long long ull;

// ---- scratch (device globals) ----
__device__ __align__(16) float g_F[ROWS*Hh];
__device__ __align__(16) float g_preA[ROWS*Hh];
__device__ __align__(16) float g_preB[ROWS*Hh];
__device__ __align__(16) float g_agg[ROWS*Hh];
__device__ int   g_cnt[ROWS];
__device__ int   g_nE;
__device__ int   g_eI[EMAX];
__device__ int   g_eJ[EMAX];
__device__ __align__(16) float g_feat[(size_t)EMAX*FST];
__device__ __align__(16) float g_Wc[NBt*256*Hh];   // folded [RW;DW], k-major rows of 128
__device__ __align__(16) float g_cvec[NBt*Hh];

__device__ __forceinline__ float silu_f(float x) { return x / (1.0f + __expf(-x)); }
__device__ __forceinline__ ull fma2(ull a, ull b, ull c) {
    ull d; asm("fma.rn.f32x2 %0, %1, %2, %3;" : "=l"(d) : "l"(a), "l"(b), "l"(c)); return d;
}
__device__ __forceinline__ ull pack2(float lo, float hi) {
    ull d; asm("mov.b64 %0, {%1, %2};" : "=l"(d) : "f"(lo), "f"(hi)); return d;
}
__device__ __forceinline__ void unpack2(ull v, float& lo, float& hi) {
    asm("mov.b64 {%0, %1}, %2;" : "=f"(lo), "=f"(hi) : "l"(v));
}

// feats = emb[idx]; preA/preB block 0; zero agg/out; reset edge counter
__global__ void k_init(const int* __restrict__ idx, const float* __restrict__ emb,
                       const float* __restrict__ ew1, float* __restrict__ out) {
    int row = blockIdx.x, h = threadIdx.x;
    __shared__ float f[Hh];
    float v = emb[idx[row]*Hh + h];
    g_F[row*Hh + h] = v;
    f[h] = v;
    if (row == 0 && h < Bq) out[h] = 0.f;
    if (row == 0 && h == 0) g_nE = 0;
    __syncthreads();
    const float* W1a = ew1;            // block 0
    const float* W1b = ew1 + Hh*Hh;
    float a = 0.f, bv = 0.f;
    #pragma unroll 4
    for (int k = 0; k < Hh; k++) {
        float fk = f[k];
        a  += fk * W1a[k*Hh + h];
        bv += fk * W1b[k*Hh + h];
    }
    g_preA[row*Hh + h] = a;
    g_preB[row*Hh + h] = bv;
    g_agg[row*Hh + h] = 0.f;
}

// flat edge list + block-invariant geometry features
__global__ void k_edges(const float* __restrict__ pos, const int* __restrict__ adj,
                        const float* __restrict__ mask,
                        const float* __restrict__ dpw, const float* __restrict__ dpb) {
    int row = blockIdx.x;
    int b = row / Nn, i = row % Nn;
    int j = threadIdx.x;
    __shared__ int s_cnt, s_base;
    if (j == 0) s_cnt = 0;
    __syncthreads();

    const float* pb = pos + (size_t)b*Nn*3;
    float xi = pb[i*3+0], yi = pb[i*3+1], zi = pb[i*3+2];
    float xj = pb[j*3+0], yj = pb[j*3+1], zj = pb[j*3+2];
    float dx = xi-xj, dy = yi-yj, dz = zi-zj;
    float dist = sqrtf(dx*dx + dy*dy + dz*dz);
    bool valid = (mask[row] > 0.f) && (mask[b*Nn + j] > 0.f) && (dist <= 5.0f)
                 && (adj[(size_t)b*Nn*Nn + (size_t)i*Nn + j] > 0) && (i != j);
    int el = -1;
    float ft[10];
    if (valid) {
        el = atomicAdd(&s_cnt, 1);
        float inv = 1.0f / (dist + 1e-8f);
        float ux = dx*inv, uy = dy*inv, uz = dz*inv;
        const float w = (5.0f/6.0f) + 1e-8f;
        #pragma unroll
        for (int r = 0; r < 6; r++) {
            float t = (dist - (float)r) / w;
            ft[r] = expf(-0.5f * t * t);
        }
        #pragma unroll
        for (int s = 0; s < 4; s++) {
            float vv = ux*dpw[0*4+s] + uy*dpw[1*4+s] + uz*dpw[2*4+s] + dpb[s];
            ft[6+s] = tanhf(vv);
        }
    }
    __syncthreads();
    if (j == 0) {
        g_cnt[row] = s_cnt;
        s_base = atomicAdd(&g_nE, s_cnt);
    }
    __syncthreads();
    if (valid) {
        int e = s_base + el;
        g_eI[e] = row;
        g_eJ[e] = b*Nn + j;
        float4* fo = (float4*)&g_feat[(size_t)e*FST];
        fo[0] = make_float4(ft[0], ft[1], ft[2], ft[3]);
        fo[1] = make_float4(ft[4], ft[5], ft[6], ft[7]);
        fo[2] = make_float4(ft[8], ft[9], 0.f, 0.f);
    }
}

// all 3 blocks' weight folding (original coalesced layout)
__global__ void k_fold(const float* __restrict__ rw2, const float* __restrict__ rb2,
                       const float* __restrict__ dw2, const float* __restrict__ db2,
                       const float* __restrict__ ew1, const float* __restrict__ eb1) {
    int h = threadIdx.x;
    int t  = blockIdx.x / 257;
    int kk = blockIdx.x % 257;
    const float* W1c = ew1 + (size_t)t*4*Hh*Hh + 2*Hh*Hh;
    const float* W1d = ew1 + (size_t)t*4*Hh*Hh + 3*Hh*Hh;
    if (kk < 256) {
        const float* src = (kk < 128) ? (rw2 + (size_t)t*Hh*Hh + kk*Hh)
                                      : (dw2 + (size_t)t*Hh*Hh + (kk-128)*Hh);
        const float* W   = (kk < 128) ? W1c : W1d;
        __shared__ float srow[Hh];
        srow[h] = src[h];
        __syncthreads();
        float s = 0.f;
        #pragma unroll 4
        for (int m = 0; m < Hh; m++) s += srow[m] * W[m*Hh + h];
        g_Wc[(t*256 + kk)*Hh + h] = s;
    } else {
        __shared__ float rb[Hh], db[Hh];
        rb[h] = rb2[t*Hh + h];
        db[h] = db2[t*Hh + h];
        __syncthreads();
        float s = eb1[t*Hh + h];
        #pragma unroll 4
        for (int m = 0; m < Hh; m++) s += rb[m]*W1c[m*Hh + h] + db[m]*W1d[m*Hh + h];
        g_cvec[t*Hh + h] = s;
    }
}

// Edge MLP + aggregation: 64-edge tiles, WH=4, warp-broadcast LDS, coalesced LDG.128 weights
__global__ void __launch_bounds__(Hh, 3)
k_edge_mlp(const float* __restrict__ rw1, const float* __restrict__ rb1,
           const float* __restrict__ dw1, const float* __restrict__ db1, int t) {
    extern __shared__ __align__(16) float sh[];   // 256*SHS floats (dynamic)
    int tid  = threadIdx.x;
    int hq   = tid & 31;       // h quad: h = 4*hq .. 4*hq+3
    int grp  = tid >> 5;       // warp = 16-edge group
    int eoff = grp * 16;

    __shared__ int s_eI[TE], s_eJ[TE];

    int nE = g_nE;
    int nT = (nE + TE - 1) / TE;
    const float* Wc = g_Wc + (size_t)t*256*Hh;
    float4 cv = *(const float4*)&g_cvec[t*Hh + 4*hq];

    for (int tile = blockIdx.x; tile < nT; tile += gridDim.x) {
        int e0 = tile * TE;
        int ne = min(TE, nE - e0);
        __syncthreads();
        if (tid < TE) {
            int idx = (tid < ne) ? (e0 + tid) : e0;
            s_eI[tid] = g_eI[idx];
            s_eJ[tid] = g_eJ[idx];
        }
        // hidden build: thread computes k=tid (rbf) and k=tid+128 (dir), all 64 edges
        {
            float rb1h = rb1[t*Hh + tid], db1h = db1[t*Hh + tid];
            float rw[6], dwv[4];
            #pragma unroll
            for (int r = 0; r < 6; r++) rw[r] = rw1[(t*6 + r)*Hh + tid];
            #pragma unroll
            for (int r = 0; r < 4; r++) dwv[r] = dw1[(t*4 + r)*Hh + tid];
            #pragma unroll
            for (int q = 0; q < 8; q++) {     // 8 chunks of 8 edges
                float va[8], vb[8];
                #pragma unroll
                for (int e = 0; e < 8; e++) {
                    int ge = q*8 + e;
                    if (ge < ne) {
                        const float4* fp = (const float4*)&g_feat[(size_t)(e0+ge)*FST];
                        float4 fa = fp[0], fb4 = fp[1], fc = fp[2];
                        float a = rb1h + fa.x*rw[0] + fa.y*rw[1] + fa.z*rw[2]
                                       + fa.w*rw[3] + fb4.x*rw[4] + fb4.y*rw[5];
                        float bb = db1h + fb4.z*dwv[0] + fb4.w*dwv[1]
                                        + fc.x*dwv[2] + fc.y*dwv[3];
                        va[e] = silu_f(a);
                        vb[e] = silu_f(bb);
                    } else { va[e] = 0.f; vb[e] = 0.f; }
                }
                float4* rowA = (float4*)&sh[tid*SHS + q*8];
                float4* rowB = (float4*)&sh[(128+tid)*SHS + q*8];
                rowA[0] = make_float4(va[0], va[1], va[2], va[3]);
                rowA[1] = make_float4(va[4], va[5], va[6], va[7]);
                rowB[0] = make_float4(vb[0], vb[1], vb[2], vb[3]);
                rowB[1] = make_float4(vb[4], vb[5], vb[6], vb[7]);
            }
        }
        __syncthreads();

        // accumulators: 4 h-components x 8 edge-pairs (16 edges)
        ull acc[4][8];
        #pragma unroll
        for (int p = 0; p < 8; p++) {
            int ea = eoff + 2*p, eb = ea + 1;
            float4 a0 = *(const float4*)&g_preA[s_eI[ea]*Hh + 4*hq];
            float4 b0 = *(const float4*)&g_preB[s_eJ[ea]*Hh + 4*hq];
            float4 a1 = *(const float4*)&g_preA[s_eI[eb]*Hh + 4*hq];
            float4 b1 = *(const float4*)&g_preB[s_eJ[eb]*Hh + 4*hq];
            acc[0][p] = pack2(a0.x + b0.x + cv.x, a1.x + b1.x + cv.x);
            acc[1][p] = pack2(a0.y + b0.y + cv.y, a1.y + b1.y + cv.y);
            acc[2][p] = pack2(a0.z + b0.z + cv.z, a1.z + b1.z + cv.z);
            acc[3][p] = pack2(a0.w + b0.w + cv.w, a1.w + b1.w + cv.w);
        }

        #pragma unroll 4
        for (int k = 0; k < 256; k++) {
            float4 w = __ldg((const float4*)&Wc[k*Hh + 4*hq]);
            ull w0 = pack2(w.x, w.x), w1 = pack2(w.y, w.y);
            ull w2 = pack2(w.z, w.z), w3 = pack2(w.w, w.w);
            const float* row = &sh[k*SHS + eoff];
            ulonglong2 sA = *(const ulonglong2*)(row);
            ulonglong2 sB = *(const ulonglong2*)(row + 4);
            ulonglong2 sC = *(const ulonglong2*)(row + 8);
            ulonglong2 sD = *(const ulonglong2*)(row + 12);
            acc[0][0]=fma2(sA.x,w0,acc[0][0]); acc[0][1]=fma2(sA.y,w0,acc[0][1]);
            acc[0][2]=fma2(sB.x,w0,acc[0][2]); acc[0][3]=fma2(sB.y,w0,acc[0][3]);
            acc[0][4]=fma2(sC.x,w0,acc[0][4]); acc[0][5]=fma2(sC.y,w0,acc[0][5]);
            acc[0][6]=fma2(sD.x,w0,acc[0][6]); acc[0][7]=fma2(sD.y,w0,acc[0][7]);
            acc[1][0]=fma2(sA.x,w1,acc[1][0]); acc[1][1]=fma2(sA.y,w1,acc[1][1]);
            acc[1][2]=fma2(sB.x,w1,acc[1][2]); acc[1][3]=fma2(sB.y,w1,acc[1][3]);
            acc[1][4]=fma2(sC.x,w1,acc[1][4]); acc[1][5]=fma2(sC.y,w1,acc[1][5]);
            acc[1][6]=fma2(sD.x,w1,acc[1][6]); acc[1][7]=fma2(sD.y,w1,acc[1][7]);
            acc[2][0]=fma2(sA.x,w2,acc[2][0]); acc[2][1]=fma2(sA.y,w2,acc[2][1]);
            acc[2][2]=fma2(sB.x,w2,acc[2][2]); acc[2][3]=fma2(sB.y,w2,acc[2][3]);
            acc[2][4]=fma2(sC.x,w2,acc[2][4]); acc[2][5]=fma2(sC.y,w2,acc[2][5]);
            acc[2][6]=fma2(sD.x,w2,acc[2][6]); acc[2][7]=fma2(sD.y,w2,acc[2][7]);
            acc[3][0]=fma2(sA.x,w3,acc[3][0]); acc[3][1]=fma2(sA.y,w3,acc[3][1]);
            acc[3][2]=fma2(sB.x,w3,acc[3][2]); acc[3][3]=fma2(sB.y,w3,acc[3][3]);
            acc[3][4]=fma2(sC.x,w3,acc[3][4]); acc[3][5]=fma2(sC.y,w3,acc[3][5]);
            acc[3][6]=fma2(sD.x,w3,acc[3][6]); acc[3][7]=fma2(sD.y,w3,acc[3][7]);
        }

        // silu + run-compressed atomic aggregation, one h-channel at a time
        int neH = ne - eoff; neH = neH < 0 ? 0 : (neH > 16 ? 16 : neH);
        #pragma unroll
        for (int c = 0; c < 4; c++) {
            float mv[16];
            #pragma unroll
            for (int p = 0; p < 8; p++) {
                float lo, hi;
                unpack2(acc[c][p], lo, hi);
                mv[2*p] = silu_f(lo); mv[2*p+1] = silu_f(hi);
            }
            int hh = 4*hq + c;
            int cur = -1; float s = 0.f;
            #pragma unroll
            for (int e = 0; e < 16; e++) {
                if (e < neH) {
                    int i = s_eI[eoff + e];
                    if (i != cur) {
                        if (cur >= 0) atomicAdd(&g_agg[cur*Hh + hh], s);
                        cur = i; s = mv[e];
                    } else s += mv[e];
                }
            }
            if (cur >= 0) atomicAdd(&g_agg[cur*Hh + hh], s);
        }
    }
}

// node update (+ next-block pre, or output head on last block)
__global__ void k_node(const float* __restrict__ ew2, const float* __restrict__ eb2,
                       const float* __restrict__ nw1, const float* __restrict__ nb1,
                       const float* __restrict__ nw2, const float* __restrict__ nb2,
                       const float* __restrict__ ew1,
                       const float* __restrict__ ow1, const float* __restrict__ ob1,
                       const float* __restrict__ ow2, const float* __restrict__ ob2,
                       const float* __restrict__ mask, float* __restrict__ out, int t) {
    int row = blockIdx.x, h = threadIdx.x;
    __shared__ float x[256];
    __shared__ float agg_s[Hh];
    __shared__ float u[Hh];
    __shared__ float red[4];
    float fh = g_F[row*Hh + h];
    x[h] = fh;
    agg_s[h] = g_agg[row*Hh + h];
    __syncthreads();
    const float* EW2 = ew2 + (size_t)t*Hh*Hh;
    float deg = (float)g_cnt[row];
    float s = deg * eb2[t*Hh + h];
    #pragma unroll 4
    for (int k = 0; k < Hh; k++) s += agg_s[k] * EW2[k*Hh + h];
    x[128 + h] = s;
    __syncthreads();
    const float* NW1 = nw1 + (size_t)t*256*Hh;
    float uacc = nb1[t*Hh + h];
    #pragma unroll 4
    for (int k = 0; k < 256; k++) uacc += x[k] * NW1[k*Hh + h];
    u[h] = silu_f(uacc);
    __syncthreads();
    const float* NW2 = nw2 + (size_t)t*Hh*Hh;
    float upd = nb2[t*Hh + h];
    #pragma unroll 4
    for (int k = 0; k < Hh; k++) upd += u[k] * NW2[k*Hh + h];
    float newf = fh + upd;
    g_F[row*Hh + h] = newf;

    __syncthreads();
    x[h] = newf;
    __syncthreads();
    if (t + 1 < NBt) {
        const float* W1a = ew1 + (size_t)(t+1)*4*Hh*Hh;
        const float* W1b = W1a + Hh*Hh;
        float a = 0.f, bv = 0.f;
        #pragma unroll 4
        for (int k = 0; k < Hh; k++) {
            float fk = x[k];
            a  += fk * W1a[k*Hh + h];
            bv += fk * W1b[k*Hh + h];
        }
        g_preA[row*Hh + h] = a;
        g_preB[row*Hh + h] = bv;
        g_agg[row*Hh + h] = 0.f;
    } else {
        float oacc = ob1[h];
        #pragma unroll 4
        for (int k = 0; k < Hh; k++) oacc += x[k] * ow1[k*Hh + h];
        float val = silu_f(oacc) * ow2[h];
        #pragma unroll
        for (int off = 16; off > 0; off >>= 1)
            val += __shfl_down_sync(0xffffffffu, val, off);
        if ((h & 31) == 0) red[h >> 5] = val;
        __syncthreads();
        if (h == 0) {
            float v = red[0] + red[1] + red[2] + red[3] + ob2[0];
            v *= mask[row];
            atomicAdd(&out[row / Nn], v);
        }
    }
}

extern "C" void kernel_launch(void* const* d_in, const int* in_sizes, int n_in,
                              void* d_out, int out_size) {
    const int*   node_indices = (const int*)  d_in[0];
    const float* positions    = (const float*)d_in[1];
    const int*   adjacency    = (const int*)  d_in[2];
    const float* mask         = (const float*)d_in[3];
    const float* emb          = (const float*)d_in[4];
    const float* dpw          = (const float*)d_in[5];
    const float* dpb          = (const float*)d_in[6];
    const float* rbf_w1 = (const float*)d_in[7];
    const float* rbf_b1 = (const float*)d_in[8];
    const float* rbf_w2 = (const float*)d_in[9];
    const float* rbf_b2 = (const float*)d_in[10];
    const float* dir_w1 = (const float*)d_in[11];
    const float* dir_b1 = (const float*)d_in[12];
    const float* dir_w2 = (const float*)d_in[13];
    const float* dir_b2 = (const float*)d_in[14];
    const float* edge_w1 = (const float*)d_in[15];
    const float* edge_b1 = (const float*)d_in[16];
    const float* edge_w2 = (const float*)d_in[17];
    const float* edge_b2 = (const float*)d_in[18];
    const float* node_w1 = (const float*)d_in[19];
    const float* node_b1 = (const float*)d_in[20];
    const float* node_w2 = (const float*)d_in[21];
    const float* node_b2 = (const float*)d_in[22];
    const float* ow1 = (const float*)d_in[23];
    const float* ob1 = (const float*)d_in[24];
    const float* ow2 = (const float*)d_in[25];
    const float* ob2 = (const float*)d_in[26];
    float* out = (float*)d_out;

    cudaFuncSetAttribute(k_edge_mlp, cudaFuncAttributeMaxDynamicSharedMemorySize, SH_BYTES);

    k_init<<<ROWS, Hh>>>(node_indices, emb, edge_w1, out);      // resets g_nE
    k_edges<<<ROWS, Nn>>>(positions, adjacency, mask, dpw, dpb);
    k_fold<<<3*257, Hh>>>(rbf_w2, rbf_b2, dir_w2, dir_b2, edge_w1, edge_b1);
    for (int t = 0; t < NBt; t++) {
        k_edge_mlp<<<GRID_E, Hh, SH_BYTES>>>(rbf_w1, rbf_b1, dir_w1, dir_b1, t);
        k_node<<<ROWS, Hh>>>(edge_w2, edge_b2, node_w1, node_b1, node_w2, node_b2,
                             edge_w1, ow1, ob1, ow2, ob2, mask, out, t);
    }
}

// round 8
// speedup vs baseline: 1.8324x; 1.1770x over previous
#include <cuda_runtime.h>
#include <math.h>

#define Bq   4
#define Nn   192
#define Hh   128
#define NBt  3
#define ROWS (Bq*Nn)       // 768
#define EMAX (ROWS*Nn)
#define TE   32            // edges per tile
#define FST  12            // feature stride (floats)
#define SHS  36            // sh row stride (floats): 144B, 16B-aligned, ≡4 mod 32 banks
#define GRID_E 740

typedef unsigned long long ull;

// ---- scratch (device globals) ----
__device__ __align__(16) float g_F[ROWS*Hh];
__device__ __align__(16) float g_preA[ROWS*Hh];
__device__ __align__(16) float g_preB[ROWS*Hh];
__device__ __align__(16) float g_agg[ROWS*Hh];
__device__ int   g_cnt[ROWS];
__device__ int   g_nE;
__device__ int   g_eI[EMAX];
__device__ int   g_eJ[EMAX];
__device__ __align__(16) float g_feat[(size_t)EMAX*FST];
__device__ __align__(16) float g_Wc[NBt*256*Hh];   // folded [RW;DW], k-major rows of 128
__device__ __align__(16) float g_cvec[NBt*Hh];

__device__ __forceinline__ float silu_f(float x) { return x / (1.0f + __expf(-x)); }
__device__ __forceinline__ ull fma2(ull a, ull b, ull c) {
    ull d; asm("fma.rn.f32x2 %0, %1, %2, %3;" : "=l"(d) : "l"(a), "l"(b), "l"(c)); return d;
}
__device__ __forceinline__ ull pack2(float lo, float hi) {
    ull d; asm("mov.b64 %0, {%1, %2};" : "=l"(d) : "f"(lo), "f"(hi)); return d;
}
__device__ __forceinline__ void unpack2(ull v, float& lo, float& hi) {
    asm("mov.b64 {%0, %1}, %2;" : "=f"(lo), "=f"(hi) : "l"(v));
}

// feats = emb[idx]; preA/preB block 0; zero agg/out; reset edge counter
__global__ void k_init(const int* __restrict__ idx, const float* __restrict__ emb,
                       const float* __restrict__ ew1, float* __restrict__ out) {
    int row = blockIdx.x, h = threadIdx.x;
    __shared__ float f[Hh];
    float v = emb[idx[row]*Hh + h];
    g_F[row*Hh + h] = v;
    f[h] = v;
    if (row == 0 && h < Bq) out[h] = 0.f;
    if (row == 0 && h == 0) g_nE = 0;
    __syncthreads();
    const float* W1a = ew1;            // block 0
    const float* W1b = ew1 + Hh*Hh;
    float a = 0.f, bv = 0.f;
    #pragma unroll 4
    for (int k = 0; k < Hh; k++) {
        float fk = f[k];
        a  += fk * W1a[k*Hh + h];
        bv += fk * W1b[k*Hh + h];
    }
    g_preA[row*Hh + h] = a;
    g_preB[row*Hh + h] = bv;
    g_agg[row*Hh + h] = 0.f;
}

// flat edge list + block-invariant geometry features
__global__ void k_edges(const float* __restrict__ pos, const int* __restrict__ adj,
                        const float* __restrict__ mask,
                        const float* __restrict__ dpw, const float* __restrict__ dpb) {
    int row = blockIdx.x;
    int b = row / Nn, i = row % Nn;
    int j = threadIdx.x;
    __shared__ int s_cnt, s_base;
    if (j == 0) s_cnt = 0;
    __syncthreads();

    const float* pb = pos + (size_t)b*Nn*3;
    float xi = pb[i*3+0], yi = pb[i*3+1], zi = pb[i*3+2];
    float xj = pb[j*3+0], yj = pb[j*3+1], zj = pb[j*3+2];
    float dx = xi-xj, dy = yi-yj, dz = zi-zj;
    float dist = sqrtf(dx*dx + dy*dy + dz*dz);
    bool valid = (mask[row] > 0.f) && (mask[b*Nn + j] > 0.f) && (dist <= 5.0f)
                 && (adj[(size_t)b*Nn*Nn + (size_t)i*Nn + j] > 0) && (i != j);
    int el = -1;
    float ft[10];
    if (valid) {
        el = atomicAdd(&s_cnt, 1);
        float inv = 1.0f / (dist + 1e-8f);
        float ux = dx*inv, uy = dy*inv, uz = dz*inv;
        const float w = (5.0f/6.0f) + 1e-8f;
        #pragma unroll
        for (int r = 0; r < 6; r++) {
            float t = (dist - (float)r) / w;
            ft[r] = expf(-0.5f * t * t);
        }
        #pragma unroll
        for (int s = 0; s < 4; s++) {
            float vv = ux*dpw[0*4+s] + uy*dpw[1*4+s] + uz*dpw[2*4+s] + dpb[s];
            ft[6+s] = tanhf(vv);
        }
    }
    __syncthreads();
    if (j == 0) {
        g_cnt[row] = s_cnt;
        s_base = atomicAdd(&g_nE, s_cnt);
    }
    __syncthreads();
    if (valid) {
        int e = s_base + el;
        g_eI[e] = row;
        g_eJ[e] = b*Nn + j;
        float4* fo = (float4*)&g_feat[(size_t)e*FST];
        fo[0] = make_float4(ft[0], ft[1], ft[2], ft[3]);
        fo[1] = make_float4(ft[4], ft[5], ft[6], ft[7]);
        fo[2] = make_float4(ft[8], ft[9], 0.f, 0.f);
    }
}

// all 3 blocks' weight folding
__global__ void k_fold(const float* __restrict__ rw2, const float* __restrict__ rb2,
                       const float* __restrict__ dw2, const float* __restrict__ db2,
                       const float* __restrict__ ew1, const float* __restrict__ eb1) {
    int h = threadIdx.x;
    int t  = blockIdx.x / 257;
    int kk = blockIdx.x % 257;
    const float* W1c = ew1 + (size_t)t*4*Hh*Hh + 2*Hh*Hh;
    const float* W1d = ew1 + (size_t)t*4*Hh*Hh + 3*Hh*Hh;
    if (kk < 256) {
        const float* src = (kk < 128) ? (rw2 + (size_t)t*Hh*Hh + kk*Hh)
                                      : (dw2 + (size_t)t*Hh*Hh + (kk-128)*Hh);
        const float* W   = (kk < 128) ? W1c : W1d;
        __shared__ float srow[Hh];
        srow[h] = src[h];
        __syncthreads();
        float s = 0.f;
        #pragma unroll 4
        for (int m = 0; m < Hh; m++) s += srow[m] * W[m*Hh + h];
        g_Wc[(t*256 + kk)*Hh + h] = s;
    } else {
        __shared__ float rb[Hh], db[Hh];
        rb[h] = rb2[t*Hh + h];
        db[h] = db2[t*Hh + h];
        __syncthreads();
        float s = eb1[t*Hh + h];
        #pragma unroll 4
        for (int m = 0; m < Hh; m++) s += rb[m]*W1c[m*Hh + h] + db[m]*W1d[m*Hh + h];
        g_cvec[t*Hh + h] = s;
    }
}

// Edge MLP + aggregation: 32-edge tiles, WH=4, 8 edges/warp, 5 CTAs/SM
__global__ void __launch_bounds__(Hh, 5)
k_edge_mlp(const float* __restrict__ rw1, const float* __restrict__ rb1,
           const float* __restrict__ dw1, const float* __restrict__ db1, int t) {
    __shared__ __align__(16) float sh[256*SHS];
    __shared__ int s_eI[TE], s_eJ[TE];
    int tid  = threadIdx.x;
    int hq   = tid & 31;       // h quad: h = 4*hq .. 4*hq+3
    int grp  = tid >> 5;       // warp = 8-edge group
    int eoff = grp * 8;

    int nE = g_nE;
    int nT = (nE + TE - 1) / TE;
    const float* Wc = g_Wc + (size_t)t*256*Hh;
    float4 cv = *(const float4*)&g_cvec[t*Hh + 4*hq];

    for (int tile = blockIdx.x; tile < nT; tile += gridDim.x) {
        int e0 = tile * TE;
        int ne = min(TE, nE - e0);
        __syncthreads();
        if (tid < TE) {
            int idx = (tid < ne) ? (e0 + tid) : e0;
            s_eI[tid] = g_eI[idx];
            s_eJ[tid] = g_eJ[idx];
        }
        // hidden build: thread computes k=tid (rbf) and k=tid+128 (dir), all 32 edges
        {
            float rb1h = rb1[t*Hh + tid], db1h = db1[t*Hh + tid];
            float rw[6], dwv[4];
            #pragma unroll
            for (int r = 0; r < 6; r++) rw[r] = rw1[(t*6 + r)*Hh + tid];
            #pragma unroll
            for (int r = 0; r < 4; r++) dwv[r] = dw1[(t*4 + r)*Hh + tid];
            #pragma unroll
            for (int q = 0; q < 4; q++) {     // 4 chunks of 8 edges
                float va[8], vb[8];
                #pragma unroll
                for (int e = 0; e < 8; e++) {
                    int ge = q*8 + e;
                    if (ge < ne) {
                        const float4* fp = (const float4*)&g_feat[(size_t)(e0+ge)*FST];
                        float4 fa = fp[0], fb4 = fp[1], fc = fp[2];
                        float a = rb1h + fa.x*rw[0] + fa.y*rw[1] + fa.z*rw[2]
                                       + fa.w*rw[3] + fb4.x*rw[4] + fb4.y*rw[5];
                        float bb = db1h + fb4.z*dwv[0] + fb4.w*dwv[1]
                                        + fc.x*dwv[2] + fc.y*dwv[3];
                        va[e] = silu_f(a);
                        vb[e] = silu_f(bb);
                    } else { va[e] = 0.f; vb[e] = 0.f; }
                }
                float4* rowA = (float4*)&sh[tid*SHS + q*8];
                float4* rowB = (float4*)&sh[(128+tid)*SHS + q*8];
                rowA[0] = make_float4(va[0], va[1], va[2], va[3]);
                rowA[1] = make_float4(va[4], va[5], va[6], va[7]);
                rowB[0] = make_float4(vb[0], vb[1], vb[2], vb[3]);
                rowB[1] = make_float4(vb[4], vb[5], vb[6], vb[7]);
            }
        }
        __syncthreads();

        // accumulators: 4 h-components x 4 edge-pairs (8 edges)
        ull acc[4][4];
        #pragma unroll
        for (int p = 0; p < 4; p++) {
            int ea = eoff + 2*p, eb = ea + 1;
            float4 a0 = *(const float4*)&g_preA[s_eI[ea]*Hh + 4*hq];
            float4 b0 = *(const float4*)&g_preB[s_eJ[ea]*Hh + 4*hq];
            float4 a1 = *(const float4*)&g_preA[s_eI[eb]*Hh + 4*hq];
            float4 b1 = *(const float4*)&g_preB[s_eJ[eb]*Hh + 4*hq];
            acc[0][p] = pack2(a0.x + b0.x + cv.x, a1.x + b1.x + cv.x);
            acc[1][p] = pack2(a0.y + b0.y + cv.y, a1.y + b1.y + cv.y);
            acc[2][p] = pack2(a0.z + b0.z + cv.z, a1.z + b1.z + cv.z);
            acc[3][p] = pack2(a0.w + b0.w + cv.w, a1.w + b1.w + cv.w);
        }

        #pragma unroll 4
        for (int k = 0; k < 256; k++) {
            float4 w = __ldg((const float4*)&Wc[k*Hh + 4*hq]);
            ull w0 = pack2(w.x, w.x), w1 = pack2(w.y, w.y);
            ull w2 = pack2(w.z, w.z), w3 = pack2(w.w, w.w);
            const float* row = &sh[k*SHS + eoff];
            ulonglong2 sA = *(const ulonglong2*)(row);
            ulonglong2 sB = *(const ulonglong2*)(row + 4);
            acc[0][0]=fma2(sA.x,w0,acc[0][0]); acc[0][1]=fma2(sA.y,w0,acc[0][1]);
            acc[0][2]=fma2(sB.x,w0,acc[0][2]); acc[0][3]=fma2(sB.y,w0,acc[0][3]);
            acc[1][0]=fma2(sA.x,w1,acc[1][0]); acc[1][1]=fma2(sA.y,w1,acc[1][1]);
            acc[1][2]=fma2(sB.x,w1,acc[1][2]); acc[1][3]=fma2(sB.y,w1,acc[1][3]);
            acc[2][0]=fma2(sA.x,w2,acc[2][0]); acc[2][1]=fma2(sA.y,w2,acc[2][1]);
            acc[2][2]=fma2(sB.x,w2,acc[2][2]); acc[2][3]=fma2(sB.y,w2,acc[2][3]);
            acc[3][0]=fma2(sA.x,w3,acc[3][0]); acc[3][1]=fma2(sA.y,w3,acc[3][1]);
            acc[3][2]=fma2(sB.x,w3,acc[3][2]); acc[3][3]=fma2(sB.y,w3,acc[3][3]);
        }

        // silu + run-compressed atomic aggregation, one h-channel at a time
        int neH = ne - eoff; neH = neH < 0 ? 0 : (neH > 8 ? 8 : neH);
        #pragma unroll
        for (int c = 0; c < 4; c++) {
            float mv[8];
            #pragma unroll
            for (int p = 0; p < 4; p++) {
                float lo, hi;
                unpack2(acc[c][p], lo, hi);
                mv[2*p] = silu_f(lo); mv[2*p+1] = silu_f(hi);
            }
            int hh = 4*hq + c;
            int cur = -1; float s = 0.f;
            #pragma unroll
            for (int e = 0; e < 8; e++) {
                if (e < neH) {
                    int i = s_eI[eoff + e];
                    if (i != cur) {
                        if (cur >= 0) atomicAdd(&g_agg[cur*Hh + hh], s);
                        cur = i; s = mv[e];
                    } else s += mv[e];
                }
            }
            if (cur >= 0) atomicAdd(&g_agg[cur*Hh + hh], s);
        }
    }
}

// node update (+ next-block pre, or output head on last block)
__global__ void k_node(const float* __restrict__ ew2, const float* __restrict__ eb2,
                       const float* __restrict__ nw1, const float* __restrict__ nb1,
                       const float* __restrict__ nw2, const float* __restrict__ nb2,
                       const float* __restrict__ ew1,
                       const float* __restrict__ ow1, const float* __restrict__ ob1,
                       const float* __restrict__ ow2, const float* __restrict__ ob2,
                       const float* __restrict__ mask, float* __restrict__ out, int t) {
    int row = blockIdx.x, h = threadIdx.x;
    __shared__ float x[256];
    __shared__ float agg_s[Hh];
    __shared__ float u[Hh];
    __shared__ float red[4];
    float fh = g_F[row*Hh + h];
    x[h] = fh;
    agg_s[h] = g_agg[row*Hh + h];
    __syncthreads();
    const float* EW2 = ew2 + (size_t)t*Hh*Hh;
    float deg = (float)g_cnt[row];
    float s = deg * eb2[t*Hh + h];
    #pragma unroll 4
    for (int k = 0; k < Hh; k++) s += agg_s[k] * EW2[k*Hh + h];
    x[128 + h] = s;
    __syncthreads();
    const float* NW1 = nw1 + (size_t)t*256*Hh;
    float uacc = nb1[t*Hh + h];
    #pragma unroll 4
    for (int k = 0; k < 256; k++) uacc += x[k] * NW1[k*Hh + h];
    u[h] = silu_f(uacc);
    __syncthreads();
    const float* NW2 = nw2 + (size_t)t*Hh*Hh;
    float upd = nb2[t*Hh + h];
    #pragma unroll 4
    for (int k = 0; k < Hh; k++) upd += u[k] * NW2[k*Hh + h];
    float newf = fh + upd;
    g_F[row*Hh + h] = newf;

    __syncthreads();
    x[h] = newf;
    __syncthreads();
    if (t + 1 < NBt) {
        const float* W1a = ew1 + (size_t)(t+1)*4*Hh*Hh;
        const float* W1b = W1a + Hh*Hh;
        float a = 0.f, bv = 0.f;
        #pragma unroll 4
        for (int k = 0; k < Hh; k++) {
            float fk = x[k];
            a  += fk * W1a[k*Hh + h];
            bv += fk * W1b[k*Hh + h];
        }
        g_preA[row*Hh + h] = a;
        g_preB[row*Hh + h] = bv;
        g_agg[row*Hh + h] = 0.f;
    } else {
        float oacc = ob1[h];
        #pragma unroll 4
        for (int k = 0; k < Hh; k++) oacc += x[k] * ow1[k*Hh + h];
        float val = silu_f(oacc) * ow2[h];
        #pragma unroll
        for (int off = 16; off > 0; off >>= 1)
            val += __shfl_down_sync(0xffffffffu, val, off);
        if ((h & 31) == 0) red[h >> 5] = val;
        __syncthreads();
        if (h == 0) {
            float v = red[0] + red[1] + red[2] + red[3] + ob2[0];
            v *= mask[row];
            atomicAdd(&out[row / Nn], v);
        }
    }
}

extern "C" void kernel_launch(void* const* d_in, const int* in_sizes, int n_in,
                              void* d_out, int out_size) {
    const int*   node_indices = (const int*)  d_in[0];
    const float* positions    = (const float*)d_in[1];
    const int*   adjacency    = (const int*)  d_in[2];
    const float* mask         = (const float*)d_in[3];
    const float* emb          = (const float*)d_in[4];
    const float* dpw          = (const float*)d_in[5];
    const float* dpb          = (const float*)d_in[6];
    const float* rbf_w1 = (const float*)d_in[7];
    const float* rbf_b1 = (const float*)d_in[8];
    const float* rbf_w2 = (const float*)d_in[9];
    const float* rbf_b2 = (const float*)d_in[10];
    const float* dir_w1 = (const float*)d_in[11];
    const float* dir_b1 = (const float*)d_in[12];
    const float* dir_w2 = (const float*)d_in[13];
    const float* dir_b2 = (const float*)d_in[14];
    const float* edge_w1 = (const float*)d_in[15];
    const float* edge_b1 = (const float*)d_in[16];
    const float* edge_w2 = (const float*)d_in[17];
    const float* edge_b2 = (const float*)d_in[18];
    const float* node_w1 = (const float*)d_in[19];
    const float* node_b1 = (const float*)d_in[20];
    const float* node_w2 = (const float*)d_in[21];
    const float* node_b2 = (const float*)d_in[22];
    const float* ow1 = (const float*)d_in[23];
    const float* ob1 = (const float*)d_in[24];
    const float* ow2 = (const float*)d_in[25];
    const float* ob2 = (const float*)d_in[26];
    float* out = (float*)d_out;

    k_init<<<ROWS, Hh>>>(node_indices, emb, edge_w1, out);      // resets g_nE
    k_edges<<<ROWS, Nn>>>(positions, adjacency, mask, dpw, dpb);
    k_fold<<<3*257, Hh>>>(rbf_w2, rbf_b2, dir_w2, dir_b2, edge_w1, edge_b1);
    for (int t = 0; t < NBt; t++) {
        k_edge_mlp<<<GRID_E, Hh>>>(rbf_w1, rbf_b1, dir_w1, dir_b1, t);
        k_node<<<ROWS, Hh>>>(edge_w2, edge_b2, node_w1, node_b1, node_w2, node_b2,
                             edge_w1, ow1, ob1, ow2, ob2, mask, out, t);
    }
}